// round 1
// baseline (speedup 1.0000x reference)
#include <cuda_runtime.h>
#include <cstdint>

#define B_ 4
#define T_ 4096
#define D_ 1024
#define M_ 1024
#define R_ (B_*T_)       // 16384 rows
#define K_ 1024
#define NCH 16
#define CHLEN (T_/NCH)   // 256
#define WSZ (M_*K_)      // 1048576

// ---------------- scratch (static device allocations; ~430MB) ----------------
__device__ float g_y [R_*D_];
__device__ float g_ig[R_*M_];
__device__ float g_og[R_*M_];
__device__ float g_r [R_*M_];
__device__ float g_xg[R_*M_];
__device__ float g_z [R_*D_];
__device__ float g_cu[B_*NCH*M_];
__device__ float g_cp[B_*NCH*M_];
__device__ float g_hi[B_*NCH*M_];
__device__ float g_wt[8*WSZ];

// ---------------- helpers ----------------
__device__ __forceinline__ float to_tf32(float x){
  uint32_t u;
  asm("cvt.rna.tf32.f32 %0, %1;" : "=r"(u) : "f"(x));
  return __uint_as_float(u);
}

__device__ __forceinline__ void cp_async16(void* sm, const void* gm){
  uint32_t sa = (uint32_t)__cvta_generic_to_shared(sm);
  asm volatile("cp.async.cg.shared.global [%0], [%1], 16;\n" :: "r"(sa), "l"(gm));
}

__device__ __forceinline__ void mma_tf32(float* c, const uint32_t* a, const uint32_t* b){
  asm volatile(
    "mma.sync.aligned.m16n8k8.row.col.f32.tf32.tf32.f32 "
    "{%0,%1,%2,%3}, {%4,%5,%6,%7}, {%8,%9}, {%0,%1,%2,%3};\n"
    : "+f"(c[0]), "+f"(c[1]), "+f"(c[2]), "+f"(c[3])
    : "r"(a[0]), "r"(a[1]), "r"(a[2]), "r"(a[3]), "r"(b[0]), "r"(b[1]));
}

// ---------------- weight rounding (fp32 -> tf32 bit pattern) ----------------
__global__ void round_copy_kernel(const float* __restrict__ src, float* __restrict__ dst, int n){
  int i = blockIdx.x*blockDim.x + threadIdx.x;
  if(i < n) dst[i] = to_tf32(src[i]);
}

// ---------------- rmsnorm: one row per block, output rounded to tf32 ----------------
__global__ void rmsnorm_kernel(const float* __restrict__ x, const float* __restrict__ w,
                               float* __restrict__ y){
  int row = blockIdx.x;
  int t   = threadIdx.x;   // 256 threads, 4 floats each
  const float4* xr = reinterpret_cast<const float4*>(x + (size_t)row*D_);
  float4 v = xr[t];
  float ss = v.x*v.x + v.y*v.y + v.z*v.z + v.w*v.w;
  #pragma unroll
  for(int o=16;o>0;o>>=1) ss += __shfl_xor_sync(0xffffffffu, ss, o);
  __shared__ float ws[8];
  if((t&31)==0) ws[t>>5] = ss;
  __syncthreads();
  float tot = 0.f;
  #pragma unroll
  for(int i=0;i<8;i++) tot += ws[i];
  float sc = rsqrtf(tot*(1.0f/D_) + 1e-6f);
  float4 wv = reinterpret_cast<const float4*>(w)[t];
  float4 o;
  o.x = to_tf32(v.x*sc*wv.x);
  o.y = to_tf32(v.y*sc*wv.y);
  o.z = to_tf32(v.z*sc*wv.z);
  o.w = to_tf32(v.w*sc*wv.w);
  reinterpret_cast<float4*>(y + (size_t)row*D_)[t] = o;
}

// ---------------- TF32 tensor-core GEMM ----------------
// C[r,n] = epilogue( sum_k A[r,k]*W[n,k] )
// A: [R_, K_] row-major (tf32-rounded fp32), W: [N, K_] row-major (tf32-rounded)
// mode: 1 = sigmoid(acc + bias); 2 = acc * aux[r,n]; 3 = resid[r,n] + acc
#define BM 128
#define BN 128
#define BKg 16
#define PAD 4

__global__ __launch_bounds__(256) void gemm_kernel(
    const float* __restrict__ A, const float* __restrict__ W,
    const float* __restrict__ bias, const float* __restrict__ aux,
    const float* __restrict__ resid, float* __restrict__ C,
    int N, int mode, int roundOut)
{
  __shared__ float As[2][BM][BKg+PAD];
  __shared__ float Bs[2][BN][BKg+PAD];
  const int tid  = threadIdx.x;
  const int wid  = tid>>5, lane = tid&31;
  const int gid  = lane>>2, tig = lane&3;
  const int wm   = wid>>2, wn = wid&3;          // 2 x 4 warp grid
  const int rowBase = blockIdx.y*BM;
  const int colBase = blockIdx.x*BN;

  float acc[4][4][4];
  #pragma unroll
  for(int i=0;i<4;i++)
    #pragma unroll
    for(int j=0;j<4;j++)
      #pragma unroll
      for(int k=0;k<4;k++) acc[i][j][k]=0.f;

  const int ldr = tid>>2;       // 0..63
  const int ldk = (tid&3)*4;    // 0,4,8,12

  // prologue: stage 0
  {
    #pragma unroll
    for(int i=0;i<2;i++){
      int row = ldr + i*64;
      cp_async16(&As[0][row][ldk], A + (size_t)(rowBase+row)*K_ + ldk);
      cp_async16(&Bs[0][row][ldk], W + (size_t)(colBase+row)*K_ + ldk);
    }
    asm volatile("cp.async.commit_group;\n");
  }

  const int NK = K_/BKg;   // 64
  for(int kt=0; kt<NK; kt++){
    const int buf = kt&1;
    if(kt+1 < NK){
      int k0 = (kt+1)*BKg;
      #pragma unroll
      for(int i=0;i<2;i++){
        int row = ldr + i*64;
        cp_async16(&As[buf^1][row][ldk], A + (size_t)(rowBase+row)*K_ + k0 + ldk);
        cp_async16(&Bs[buf^1][row][ldk], W + (size_t)(colBase+row)*K_ + k0 + ldk);
      }
      asm volatile("cp.async.commit_group;\n");
      asm volatile("cp.async.wait_group 1;\n");
    } else {
      asm volatile("cp.async.wait_group 0;\n");
    }
    __syncthreads();

    #pragma unroll
    for(int ks=0; ks<2; ks++){
      const int k0 = ks*8;
      uint32_t af[4][4], bf[4][2];
      #pragma unroll
      for(int mt=0; mt<4; mt++){
        int rb = wm*64 + mt*16;
        af[mt][0] = __float_as_uint(As[buf][rb+gid  ][k0+tig  ]);
        af[mt][1] = __float_as_uint(As[buf][rb+gid+8][k0+tig  ]);
        af[mt][2] = __float_as_uint(As[buf][rb+gid  ][k0+tig+4]);
        af[mt][3] = __float_as_uint(As[buf][rb+gid+8][k0+tig+4]);
      }
      #pragma unroll
      for(int nt=0; nt<4; nt++){
        int nb = wn*32 + nt*8 + gid;
        bf[nt][0] = __float_as_uint(Bs[buf][nb][k0+tig  ]);
        bf[nt][1] = __float_as_uint(Bs[buf][nb][k0+tig+4]);
      }
      #pragma unroll
      for(int mt=0; mt<4; mt++)
        #pragma unroll
        for(int nt=0; nt<4; nt++)
          mma_tf32(acc[mt][nt], af[mt], bf[nt]);
    }
    __syncthreads();
  }

  // epilogue
  #pragma unroll
  for(int mt=0; mt<4; mt++){
    #pragma unroll
    for(int nt=0; nt<4; nt++){
      #pragma unroll
      for(int half=0; half<2; half++){
        int rr = rowBase + wm*64 + mt*16 + gid + half*8;
        int cc = colBase + wn*32 + nt*8 + 2*tig;
        size_t idx = (size_t)rr*N + cc;
        float v0 = acc[mt][nt][half*2+0];
        float v1 = acc[mt][nt][half*2+1];
        if(mode==1){
          v0 += bias[cc]; v1 += bias[cc+1];
          v0 = 1.f/(1.f+__expf(-v0));
          v1 = 1.f/(1.f+__expf(-v1));
        } else if(mode==2){
          v0 *= aux[idx]; v1 *= aux[idx+1];
        } else if(mode==3){
          v0 += resid[idx]; v1 += resid[idx+1];
        }
        if(roundOut){ v0 = to_tf32(v0); v1 = to_tf32(v1); }
        C[idx]   = v0;
        C[idx+1] = v1;
      }
    }
  }
}

// ---------------- chunked linear recurrence ----------------
// h_t = xg_t + r_t * h_{t-1};  channel = (b,m), chunked over T
__global__ void scan1_kernel(const float* __restrict__ xg, const float* __restrict__ rg){
  int g = blockIdx.x*blockDim.x + threadIdx.x;      // B_*NCH*M_ = 65536
  int m = g & (M_-1);
  int c = (g >> 10) & (NCH-1);
  int b = g >> 14;
  size_t base = ((size_t)(b*T_ + c*CHLEN))*M_ + m;
  float u = 0.f, P = 1.f;
  #pragma unroll 8
  for(int t=0;t<CHLEN;t++){
    float rv = rg[base], xv = xg[base];
    u = xv + rv*u;
    P *= rv;
    base += M_;
  }
  g_cu[g] = u; g_cp[g] = P;
}

__global__ void scan2_kernel(const float* __restrict__ mem, float* __restrict__ memout){
  int g = blockIdx.x*blockDim.x + threadIdx.x;      // B_*M_ = 4096
  int m = g & (M_-1);
  int b = g >> 10;
  float h = mem[g];
  #pragma unroll
  for(int c=0;c<NCH;c++){
    int ci = (b*NCH + c)*M_ + m;
    g_hi[ci] = h;
    h = g_cu[ci] + g_cp[ci]*h;
  }
  memout[g] = h;                                    // h[:, T-1]
}

// replay each chunk with its true init; fuse s = softsign(h)*og, overwrite xg with s (tf32-rounded)
__global__ void scan3_kernel(float* __restrict__ xg, const float* __restrict__ rg,
                             const float* __restrict__ og){
  int g = blockIdx.x*blockDim.x + threadIdx.x;
  int m = g & (M_-1);
  int c = (g >> 10) & (NCH-1);
  int b = g >> 14;
  float h = g_hi[g];
  size_t base = ((size_t)(b*T_ + c*CHLEN))*M_ + m;
  #pragma unroll 4
  for(int t=0;t<CHLEN;t++){
    float rv = rg[base], xv = xg[base];
    h = xv + rv*h;
    float s = h/(1.f + fabsf(h)) * og[base];
    xg[base] = to_tf32(s);
    base += M_;
  }
}

// ---------------- host ----------------
extern "C" void kernel_launch(void* const* d_in, const int* in_sizes, int n_in,
                              void* d_out, int out_size){
  (void)in_sizes; (void)n_in; (void)out_size;
  const float* x        = (const float*)d_in[0];
  const float* mem      = (const float*)d_in[1];
  const float* norm_w   = (const float*)d_in[2];
  const float* wr_w     = (const float*)d_in[3];
  const float* wr_b     = (const float*)d_in[4];
  const float* wi_w     = (const float*)d_in[5];
  const float* wig_w    = (const float*)d_in[6];
  const float* wig_b    = (const float*)d_in[7];
  const float* wog_w    = (const float*)d_in[8];
  const float* wog_b    = (const float*)d_in[9];
  const float* wo_w     = (const float*)d_in[10];
  const float* ffnorm_w = (const float*)d_in[11];
  const float* ffn_wi_w = (const float*)d_in[12];
  const float* ffn_wg_w = (const float*)d_in[13];
  const float* ffn_wg_b = (const float*)d_in[14];
  const float* ffn_wo_w = (const float*)d_in[15];

  float* out_x   = (float*)d_out;
  float* out_mem = out_x + (size_t)R_*D_;

  float *y,*ig,*og,*r,*xg,*z,*wt;
  cudaGetSymbolAddress((void**)&y,  g_y);
  cudaGetSymbolAddress((void**)&ig, g_ig);
  cudaGetSymbolAddress((void**)&og, g_og);
  cudaGetSymbolAddress((void**)&r,  g_r);
  cudaGetSymbolAddress((void**)&xg, g_xg);
  cudaGetSymbolAddress((void**)&z,  g_z);
  cudaGetSymbolAddress((void**)&wt, g_wt);

  float* W_wig = wt + 0*(size_t)WSZ;
  float* W_wog = wt + 1*(size_t)WSZ;
  float* W_wr  = wt + 2*(size_t)WSZ;
  float* W_wi  = wt + 3*(size_t)WSZ;
  float* W_wo  = wt + 4*(size_t)WSZ;
  float* W_fg  = wt + 5*(size_t)WSZ;
  float* W_fi  = wt + 6*(size_t)WSZ;
  float* W_fo  = wt + 7*(size_t)WSZ;

  const int cpB = WSZ/256;
  round_copy_kernel<<<cpB,256>>>(wig_w,    W_wig, WSZ);
  round_copy_kernel<<<cpB,256>>>(wog_w,    W_wog, WSZ);
  round_copy_kernel<<<cpB,256>>>(wr_w,     W_wr,  WSZ);
  round_copy_kernel<<<cpB,256>>>(wi_w,     W_wi,  WSZ);
  round_copy_kernel<<<cpB,256>>>(wo_w,     W_wo,  WSZ);
  round_copy_kernel<<<cpB,256>>>(ffn_wg_w, W_fg,  WSZ);
  round_copy_kernel<<<cpB,256>>>(ffn_wi_w, W_fi,  WSZ);
  round_copy_kernel<<<cpB,256>>>(ffn_wo_w, W_fo,  WSZ);

  // --- sqrll branch ---
  rmsnorm_kernel<<<R_,256>>>(x, norm_w, y);

  dim3 gg(M_/BN, R_/BM);   // (8, 128)
  gemm_kernel<<<gg,256>>>(y, W_wig, wig_b, nullptr, nullptr, ig, M_, 1, 0);  // ig = sig(y@wig+b)
  gemm_kernel<<<gg,256>>>(y, W_wog, wog_b, nullptr, nullptr, og, M_, 1, 0);  // og
  gemm_kernel<<<gg,256>>>(y, W_wr,  wr_b,  nullptr, nullptr, r,  M_, 1, 0);  // r
  gemm_kernel<<<gg,256>>>(y, W_wi,  nullptr, ig,    nullptr, xg, M_, 2, 0);  // xg = (y@wi)*ig

  scan1_kernel<<<(B_*NCH*M_)/256,256>>>(xg, r);
  scan2_kernel<<<(B_*M_)/256,256>>>(mem, out_mem);
  scan3_kernel<<<(B_*NCH*M_)/256,256>>>(xg, r, og);   // xg now holds s (tf32-rounded)

  gemm_kernel<<<gg,256>>>(xg, W_wo, nullptr, nullptr, x, out_x, D_, 3, 0);   // x_mid = x + s@wo^T

  // --- FFN branch ---
  rmsnorm_kernel<<<R_,256>>>(out_x, ffnorm_w, z);
  gemm_kernel<<<gg,256>>>(z, W_fg, ffn_wg_b, nullptr, nullptr, ig, M_, 1, 0); // g2 = sig(z@wg+b)
  gemm_kernel<<<gg,256>>>(z, W_fi, nullptr, ig, nullptr, r, M_, 2, 1);        // ff = (z@wi)*g2 (tf32)
  gemm_kernel<<<gg,256>>>(r, W_fo, nullptr, nullptr, out_x, out_x, D_, 3, 0); // x += ff@wo^T (in place)
}

// round 2
// speedup vs baseline: 2.1470x; 2.1470x over previous
#include <cuda_runtime.h>
#include <cuda_fp16.h>
#include <cstdint>

#define B_ 4
#define T_ 4096
#define D_ 1024
#define M_ 1024
#define R_ (B_*T_)       // 16384 rows
#define K_ 1024
#define NCH 16
#define CHLEN (T_/NCH)   // 256
#define WSZ (M_*K_)      // 1048576

// ---------------- scratch ----------------
__device__ __half g_y [R_*D_];
__device__ __half g_z [R_*D_];
__device__ __half g_s [R_*M_];
__device__ __half g_ff[R_*M_];
__device__ float  g_ig[R_*M_];   // reused as fgact in FFN phase
__device__ float  g_og[R_*M_];   // reused as fiout in FFN phase
__device__ float  g_r [R_*M_];
__device__ float  g_wi[R_*M_];   // raw wi output (pre-gate)
__device__ float  g_cu[B_*NCH*M_];
__device__ float  g_cp[B_*NCH*M_];
__device__ float  g_hi[B_*NCH*M_];
__device__ __half g_wt[8*WSZ];   // packed fp16 weights

// ---------------- helpers ----------------
__device__ __forceinline__ uint32_t smem_u32(const void* p){
  return (uint32_t)__cvta_generic_to_shared(p);
}
__device__ __forceinline__ void cp_async16(uint32_t sm, const void* gm){
  asm volatile("cp.async.cg.shared.global [%0], [%1], 16;\n" :: "r"(sm), "l"(gm));
}
__device__ __forceinline__ void ldm_x4(uint32_t& r0, uint32_t& r1, uint32_t& r2, uint32_t& r3, uint32_t addr){
  asm volatile("ldmatrix.sync.aligned.m8n8.x4.shared.b16 {%0,%1,%2,%3}, [%4];\n"
    : "=r"(r0), "=r"(r1), "=r"(r2), "=r"(r3) : "r"(addr));
}
__device__ __forceinline__ void mma_f16(float* c, const uint32_t* a, const uint32_t* b){
  asm volatile(
    "mma.sync.aligned.m16n8k16.row.col.f32.f16.f16.f32 "
    "{%0,%1,%2,%3}, {%4,%5,%6,%7}, {%8,%9}, {%0,%1,%2,%3};\n"
    : "+f"(c[0]), "+f"(c[1]), "+f"(c[2]), "+f"(c[3])
    : "r"(a[0]), "r"(a[1]), "r"(a[2]), "r"(a[3]), "r"(b[0]), "r"(b[1]));
}

// ---------------- weight convert: 8x [1M] fp32 -> packed fp16 ----------------
struct Ptr8 { const float* p[8]; };
__global__ void wcvt_kernel(Ptr8 srcs, __half* __restrict__ dst){
  int i = blockIdx.x*blockDim.x + threadIdx.x;   // over 8M/4
  int e = i*4;
  int which = e >> 20;
  int off   = e & (WSZ-1);
  float4 v = *reinterpret_cast<const float4*>(srcs.p[which] + off);
  __half2 h0 = __floats2half2_rn(v.x, v.y);
  __half2 h1 = __floats2half2_rn(v.z, v.w);
  uint2 u; u.x = *(uint32_t*)&h0; u.y = *(uint32_t*)&h1;
  *reinterpret_cast<uint2*>(dst + e) = u;
}

// ---------------- rmsnorm: fp32 in -> fp16 out ----------------
__global__ void rmsnorm_kernel(const float* __restrict__ x, const float* __restrict__ w,
                               __half* __restrict__ y){
  int row = blockIdx.x;
  int t   = threadIdx.x;   // 256 threads, 4 floats each
  const float4* xr = reinterpret_cast<const float4*>(x + (size_t)row*D_);
  float4 v = xr[t];
  float ss = v.x*v.x + v.y*v.y + v.z*v.z + v.w*v.w;
  #pragma unroll
  for(int o=16;o>0;o>>=1) ss += __shfl_xor_sync(0xffffffffu, ss, o);
  __shared__ float ws[8];
  if((t&31)==0) ws[t>>5] = ss;
  __syncthreads();
  float tot = 0.f;
  #pragma unroll
  for(int i=0;i<8;i++) tot += ws[i];
  float sc = rsqrtf(tot*(1.0f/D_) + 1e-6f);
  float4 wv = reinterpret_cast<const float4*>(w)[t];
  __half2 h0 = __floats2half2_rn(v.x*sc*wv.x, v.y*sc*wv.y);
  __half2 h1 = __floats2half2_rn(v.z*sc*wv.z, v.w*sc*wv.w);
  uint2 u; u.x = *(uint32_t*)&h0; u.y = *(uint32_t*)&h1;
  *reinterpret_cast<uint2*>(y + (size_t)row*D_ + t*4) = u;
}

// ---------------- fp16 tensor-core GEMM, 128x128x64 tiles ----------------
// C[r, nglobal] = epi( sum_k A[r,k] * W[nglobal,k] )
// Output fans out to up to 4 gate buffers of width 1024: gate = nglobal>>10.
#define BM 128
#define BN 128
#define BKh 64
#define TILEB (128*64*2)   // bytes per tile per stage

__global__ __launch_bounds__(256,2) void hgemm_kernel(
    const __half* __restrict__ A, const __half* __restrict__ W, int N,
    float* o0, float* o1, float* o2, float* o3,
    const float* b0, const float* b1, const float* b2, const float* b3,
    int sigmask, const float* __restrict__ resid)
{
  extern __shared__ char smem[];
  const uint32_t asB = smem_u32(smem);
  const uint32_t bsB = asB + 2*TILEB;

  const int tid  = threadIdx.x;
  const int wid  = tid>>5, lane = tid&31;
  const int gid  = lane>>2, tig = lane&3;
  const int wm   = wid>>2, wn = wid&3;          // 2 x 4 warp grid, warp tile 64x32
  const int rowBase = blockIdx.y*BM;
  const int colBase = blockIdx.x*BN;

  float acc[4][4][4];
  #pragma unroll
  for(int i=0;i<4;i++)
    #pragma unroll
    for(int j=0;j<4;j++){ acc[i][j][0]=0.f; acc[i][j][1]=0.f; acc[i][j][2]=0.f; acc[i][j][3]=0.f; }

  // cp.async mapping: 32 rows per pass, 8 chunks (16B each) per 128B row
  const int ldr0 = tid>>3;     // 0..31
  const int ldch = tid&7;      // chunk
  const __half* Agb = A + (size_t)(rowBase + ldr0)*K_ + ldch*8;
  const __half* Wgb = W + (size_t)(colBase + ldr0)*K_ + ldch*8;

  // ldmatrix per-thread geometry
  const int j8  = lane>>3;         // matrix index 0..3
  const int il  = lane&7;
  const int mrowOff = il + ((j8&1)<<3);
  const int cA      = j8>>1;
  const int nrowOff = il + ((j8>>1)<<3);
  const int cB      = j8&1;

  int aoff[4], a7[4];
  #pragma unroll
  for(int mt=0; mt<4; mt++){
    int ar = wm*64 + mt*16 + mrowOff;
    aoff[mt] = ar*128; a7[mt] = ar&7;
  }
  int boff[2], b7[2];
  #pragma unroll
  for(int p=0; p<2; p++){
    int br = wn*32 + p*16 + nrowOff;
    boff[p] = br*128; b7[p] = br&7;
  }

  // prologue: stage 0
  {
    #pragma unroll
    for(int p=0; p<4; p++){
      int r = ldr0 + p*32;
      uint32_t da = asB + r*128 + ((ldch ^ (r&7))<<4);
      uint32_t db = bsB + r*128 + ((ldch ^ (r&7))<<4);
      cp_async16(da, Agb + (size_t)p*32*K_);
      cp_async16(db, Wgb + (size_t)p*32*K_);
    }
    asm volatile("cp.async.commit_group;\n");
  }

  const int NKT = K_/BKh;   // 16
  for(int kt=0; kt<NKT; kt++){
    const int buf = kt&1;
    if(kt+1 < NKT){
      int k0 = (kt+1)*BKh;
      uint32_t stoff = (buf^1)*TILEB;
      #pragma unroll
      for(int p=0; p<4; p++){
        int r = ldr0 + p*32;
        uint32_t da = asB + stoff + r*128 + ((ldch ^ (r&7))<<4);
        uint32_t db = bsB + stoff + r*128 + ((ldch ^ (r&7))<<4);
        cp_async16(da, Agb + (size_t)p*32*K_ + k0);
        cp_async16(db, Wgb + (size_t)p*32*K_ + k0);
      }
      asm volatile("cp.async.commit_group;\n");
      asm volatile("cp.async.wait_group 1;\n");
    } else {
      asm volatile("cp.async.wait_group 0;\n");
    }
    __syncthreads();

    const uint32_t bufA = asB + buf*TILEB;
    const uint32_t bufB = bsB + buf*TILEB;

    #pragma unroll
    for(int ks=0; ks<4; ks++){
      const int cb = ks*2;
      uint32_t a[4][4], b[4][2];
      #pragma unroll
      for(int mt=0; mt<4; mt++){
        uint32_t addr = bufA + aoff[mt] + ((uint32_t)((cb + cA) ^ a7[mt])<<4);
        ldm_x4(a[mt][0], a[mt][1], a[mt][2], a[mt][3], addr);
      }
      #pragma unroll
      for(int p=0; p<2; p++){
        uint32_t addr = bufB + boff[p] + ((uint32_t)((cb + cB) ^ b7[p])<<4);
        uint32_t r0,r1,r2,r3;
        ldm_x4(r0, r1, r2, r3, addr);
        b[p*2+0][0]=r0; b[p*2+0][1]=r1;
        b[p*2+1][0]=r2; b[p*2+1][1]=r3;
      }
      #pragma unroll
      for(int mt=0; mt<4; mt++)
        #pragma unroll
        for(int nt=0; nt<4; nt++)
          mma_f16(acc[mt][nt], a[mt], b[nt]);
    }
    __syncthreads();
  }

  // epilogue: route to gate buffer
  const int gate = colBase >> 10;
  float* outp    = (gate==0)?o0:(gate==1)?o1:(gate==2)?o2:o3;
  const float* bp = (gate==0)?b0:(gate==1)?b1:(gate==2)?b2:b3;
  const int sig  = (sigmask>>gate)&1;
  const int ccb  = colBase & 1023;

  #pragma unroll
  for(int mt=0; mt<4; mt++){
    #pragma unroll
    for(int nt=0; nt<4; nt++){
      #pragma unroll
      for(int hf=0; hf<2; hf++){
        int rr = rowBase + wm*64 + mt*16 + gid + hf*8;
        int cc = ccb + wn*32 + nt*8 + 2*tig;
        size_t idx = (size_t)rr*1024 + cc;
        float v0 = acc[mt][nt][hf*2+0];
        float v1 = acc[mt][nt][hf*2+1];
        if(bp){ v0 += bp[cc]; v1 += bp[cc+1]; }
        if(sig){
          v0 = 1.f/(1.f+__expf(-v0));
          v1 = 1.f/(1.f+__expf(-v1));
        }
        if(resid){ v0 += resid[idx]; v1 += resid[idx+1]; }
        outp[idx]   = v0;
        outp[idx+1] = v1;
      }
    }
  }
}

// ---------------- chunked linear recurrence (xg = wiout * ig computed inline) ----------------
__global__ void scan1_kernel(const float* __restrict__ wi, const float* __restrict__ ig,
                             const float* __restrict__ rg){
  int g = blockIdx.x*blockDim.x + threadIdx.x;      // 65536
  int m = g & (M_-1);
  int c = (g >> 10) & (NCH-1);
  int b = g >> 14;
  size_t base = ((size_t)(b*T_ + c*CHLEN))*M_ + m;
  float u = 0.f, P = 1.f;
  #pragma unroll 8
  for(int t=0;t<CHLEN;t++){
    float rv = rg[base];
    float xv = wi[base]*ig[base];
    u = xv + rv*u;
    P *= rv;
    base += M_;
  }
  g_cu[g] = u; g_cp[g] = P;
}

__global__ void scan2_kernel(const float* __restrict__ mem, float* __restrict__ memout){
  int g = blockIdx.x*blockDim.x + threadIdx.x;      // 4096
  int m = g & (M_-1);
  int b = g >> 10;
  float h = mem[g];
  #pragma unroll
  for(int c=0;c<NCH;c++){
    int ci = (b*NCH + c)*M_ + m;
    g_hi[ci] = h;
    h = g_cu[ci] + g_cp[ci]*h;
  }
  memout[g] = h;
}

__global__ void scan3_kernel(const float* __restrict__ wi, const float* __restrict__ ig,
                             const float* __restrict__ rg, const float* __restrict__ og,
                             __half* __restrict__ s){
  int g = blockIdx.x*blockDim.x + threadIdx.x;
  int m = g & (M_-1);
  int c = (g >> 10) & (NCH-1);
  int b = g >> 14;
  float h = g_hi[g];
  size_t base = ((size_t)(b*T_ + c*CHLEN))*M_ + m;
  #pragma unroll 4
  for(int t=0;t<CHLEN;t++){
    float rv = rg[base];
    float xv = wi[base]*ig[base];
    h = xv + rv*h;
    float sv = h/(1.f + fabsf(h)) * og[base];
    s[base] = __float2half_rn(sv);
    base += M_;
  }
}

// ---------------- ff = fiout * fgact -> fp16 ----------------
__global__ void ffmul_kernel(const float* __restrict__ fi, const float* __restrict__ fg,
                             __half* __restrict__ ff){
  int i = blockIdx.x*blockDim.x + threadIdx.x;   // over R*M/4
  int e = i*4;
  float4 a = *reinterpret_cast<const float4*>(fi + e);
  float4 b = *reinterpret_cast<const float4*>(fg + e);
  __half2 h0 = __floats2half2_rn(a.x*b.x, a.y*b.y);
  __half2 h1 = __floats2half2_rn(a.z*b.z, a.w*b.w);
  uint2 u; u.x = *(uint32_t*)&h0; u.y = *(uint32_t*)&h1;
  *reinterpret_cast<uint2*>(ff + e) = u;
}

// ---------------- host ----------------
extern "C" void kernel_launch(void* const* d_in, const int* in_sizes, int n_in,
                              void* d_out, int out_size){
  (void)in_sizes; (void)n_in; (void)out_size;
  const float* x        = (const float*)d_in[0];
  const float* mem      = (const float*)d_in[1];
  const float* norm_w   = (const float*)d_in[2];
  const float* wr_w     = (const float*)d_in[3];
  const float* wr_b     = (const float*)d_in[4];
  const float* wi_w     = (const float*)d_in[5];
  const float* wig_w    = (const float*)d_in[6];
  const float* wig_b    = (const float*)d_in[7];
  const float* wog_w    = (const float*)d_in[8];
  const float* wog_b    = (const float*)d_in[9];
  const float* wo_w     = (const float*)d_in[10];
  const float* ffnorm_w = (const float*)d_in[11];
  const float* ffn_wi_w = (const float*)d_in[12];
  const float* ffn_wg_w = (const float*)d_in[13];
  const float* ffn_wg_b = (const float*)d_in[14];
  const float* ffn_wo_w = (const float*)d_in[15];

  float* out_x   = (float*)d_out;
  float* out_mem = out_x + (size_t)R_*D_;

  __half *y,*z,*s,*ff,*wt;
  float *ig,*og,*r,*wi;
  cudaGetSymbolAddress((void**)&y,  g_y);
  cudaGetSymbolAddress((void**)&z,  g_z);
  cudaGetSymbolAddress((void**)&s,  g_s);
  cudaGetSymbolAddress((void**)&ff, g_ff);
  cudaGetSymbolAddress((void**)&ig, g_ig);
  cudaGetSymbolAddress((void**)&og, g_og);
  cudaGetSymbolAddress((void**)&r,  g_r);
  cudaGetSymbolAddress((void**)&wi, g_wi);
  cudaGetSymbolAddress((void**)&wt, g_wt);

  cudaFuncSetAttribute(hgemm_kernel, cudaFuncAttributeMaxDynamicSharedMemorySize, 4*TILEB);

  // packed weight layout (fp16): [wig|wog|wr|wi|wo|fg|fi|fo]
  Ptr8 srcs;
  srcs.p[0]=wig_w; srcs.p[1]=wog_w; srcs.p[2]=wr_w; srcs.p[3]=wi_w;
  srcs.p[4]=wo_w;  srcs.p[5]=ffn_wg_w; srcs.p[6]=ffn_wi_w; srcs.p[7]=ffn_wo_w;
  wcvt_kernel<<<(8*WSZ/4)/256,256>>>(srcs, wt);

  // --- sqrll branch ---
  rmsnorm_kernel<<<R_,256>>>(x, norm_w, y);

  // fused gates GEMM: N=4096 -> ig(sig+b), og(sig+b), r(sig+b), wiout(plain)
  {
    dim3 gg(4096/BN, R_/BM);
    hgemm_kernel<<<gg,256,4*TILEB>>>(y, wt, 4096,
        ig, og, r, wi,
        wig_b, wog_b, wr_b, nullptr,
        0x7, nullptr);
  }

  scan1_kernel<<<(B_*NCH*M_)/256,256>>>(wi, ig, r);
  scan2_kernel<<<(B_*M_)/256,256>>>(mem, out_mem);
  scan3_kernel<<<(B_*NCH*M_)/256,256>>>(wi, ig, r, og, s);

  // x_mid = x + s @ wo^T
  {
    dim3 gg(1024/BN, R_/BM);
    hgemm_kernel<<<gg,256,4*TILEB>>>(s, wt + 4*(size_t)WSZ, 1024,
        out_x, nullptr, nullptr, nullptr,
        nullptr, nullptr, nullptr, nullptr,
        0, x);
  }

  // --- FFN branch ---
  rmsnorm_kernel<<<R_,256>>>(out_x, ffnorm_w, z);

  // fused FFN GEMM: N=2048 -> fgact(sig+b) [reuse ig], fiout [reuse og]
  {
    dim3 gg(2048/BN, R_/BM);
    hgemm_kernel<<<gg,256,4*TILEB>>>(z, wt + 5*(size_t)WSZ, 2048,
        ig, og, nullptr, nullptr,
        ffn_wg_b, nullptr, nullptr, nullptr,
        0x1, nullptr);
  }

  ffmul_kernel<<<(R_*M_/4)/256,256>>>(og, ig, ff);

  // out_x += ff @ fo^T (in place)
  {
    dim3 gg(1024/BN, R_/BM);
    hgemm_kernel<<<gg,256,4*TILEB>>>(ff, wt + 7*(size_t)WSZ, 1024,
        out_x, nullptr, nullptr, nullptr,
        nullptr, nullptr, nullptr, nullptr,
        0, out_x);
  }
}